// round 4
// baseline (speedup 1.0000x reference)
#include <cuda_runtime.h>
#include <math.h>

#define BATCH 4
#define C     64
#define H     160
#define W     160
#define HW    (H*W)
#define DG    4
#define KKTAP 9
#define CG    16
#define CO2   108    // 3*DG*KK
#define JDIM  576    // DG*CG*KK
#define NT    128    // k34 pixel tile

// ---- scratch (no cudaMalloc allowed) ----
__device__ float g_off [BATCH * C   * HW];   // 26 MB : 1x1 conv + BN output
__device__ float g_com [BATCH * CO2 * HW];   // 44 MB : 3x3 conv output
__device__ float g_wt  [JDIM * C];           // w_dcn reordered: [(g,k,c)][oc]
__device__ float g_feaT[BATCH * DG * HW * CG]; // 26 MB : fea NHWC-per-group

// ---------- packed f32x2 helpers ----------
__device__ __forceinline__ unsigned long long pack2(float lo, float hi) {
    unsigned long long r;
    asm("mov.b64 %0, {%1, %2};" : "=l"(r) : "f"(lo), "f"(hi));
    return r;
}
__device__ __forceinline__ void unpack2(unsigned long long v, float& lo, float& hi) {
    asm("mov.b64 {%0, %1}, %2;" : "=f"(lo), "=f"(hi) : "l"(v));
}
__device__ __forceinline__ void fma2(unsigned long long& d,
                                     unsigned long long a,
                                     unsigned long long b) {
    asm("fma.rn.f32x2 %0, %1, %2, %0;" : "+l"(d) : "l"(a), "l"(b));
}

// ============================================================
// K0a: reorder w_dcn[oc][(g,c,k)] -> g_wt[(g,k,c)][oc]
// ============================================================
__global__ __launch_bounds__(256) void k0a_wt(const float* __restrict__ w_dcn)
{
    int idx = blockIdx.x * 256 + threadIdx.x;
    if (idx >= JDIM * C) return;
    int row = idx >> 6;      // (g,k,c)
    int oc  = idx & 63;
    int g = row / (KKTAP * CG);
    int r = row - g * (KKTAP * CG);
    int k = r / CG;
    int c = r - k * CG;
    g_wt[idx] = w_dcn[(size_t)oc * JDIM + (g * CG + c) * KKTAP + k];
}

// ============================================================
// K0b: fea NCHW -> NHWC-per-group: g_feaT[b][g][p][c16]
// ============================================================
__global__ __launch_bounds__(256) void k0b_feaT(const float* __restrict__ fea)
{
    __shared__ float s[16][65];
    int t = threadIdx.x;
    int b = blockIdx.z, g = blockIdx.y;
    int base = blockIdx.x * 64;
    #pragma unroll
    for (int r = 0; r < 4; r++) {
        int idx = t + r * 256;
        int c = idx >> 6, p = idx & 63;
        s[c][p] = fea[((size_t)(b * C + g * CG + c)) * HW + base + p];
    }
    __syncthreads();
    int p = t >> 2, q = (t & 3) * 4;
    float4 v = make_float4(s[q][p], s[q+1][p], s[q+2][p], s[q+3][p]);
    *(float4*)(g_feaT + (((size_t)(b * DG + g) * HW) + base + p) * CG + q) = v;
}

// ============================================================
// K1: off_feat = BN(fea @ w_off)
// ============================================================
__global__ __launch_bounds__(256) void k1_pointwise(
    const float* __restrict__ fea, const float* __restrict__ w_off,
    const float* __restrict__ gamma, const float* __restrict__ beta,
    const float* __restrict__ mean, const float* __restrict__ var)
{
    __shared__ float ws[64 * 64];
    __shared__ float sc[64], sh[64];
    int t = threadIdx.x;
    for (int idx = t; idx < 4096; idx += 256) {
        int o = idx & 63, i = idx >> 6;
        ws[i * 64 + o] = w_off[o * 64 + i];
    }
    if (t < 64) {
        float inv = gamma[t] * rsqrtf(var[t] + 1e-5f);
        sc[t] = inv;
        sh[t] = beta[t] - mean[t] * inv;
    }
    __syncthreads();

    int b = blockIdx.y;
    int p = blockIdx.x * 256 + t;
    const float* fb = fea + (size_t)b * C * HW + p;

    unsigned long long acc[32];
    #pragma unroll
    for (int o = 0; o < 32; o++) acc[o] = 0ull;

    #pragma unroll 4
    for (int i = 0; i < 64; i++) {
        float a = fb[(size_t)i * HW];
        unsigned long long a2 = pack2(a, a);
        const ulonglong2* w2 = (const ulonglong2*)(ws + i * 64);
        #pragma unroll
        for (int o4 = 0; o4 < 16; o4++) {
            ulonglong2 w = w2[o4];
            fma2(acc[2*o4+0], a2, w.x);
            fma2(acc[2*o4+1], a2, w.y);
        }
    }
    float* ob = g_off + (size_t)b * C * HW + p;
    #pragma unroll
    for (int o = 0; o < 32; o++) {
        float lo, hi;
        unpack2(acc[o], lo, hi);
        ob[(size_t)(2*o  ) * HW] = lo * sc[2*o  ] + sh[2*o  ];
        ob[(size_t)(2*o+1) * HW] = hi * sc[2*o+1] + sh[2*o+1];
    }
}

// ============================================================
// K2: com = conv3x3(off_feat, w_com) + b_com   (64 -> 108 ch)
// ============================================================
#define TW  32
#define TH  16
#define OCT 12
#define ICT 8

__global__ __launch_bounds__(256) void k2_conv3x3(
    const float* __restrict__ w_com, const float* __restrict__ b_com)
{
    __shared__ float in_s[ICT][TH+2][TW+2];
    __shared__ float w_s[ICT * 9 * OCT];
    int t   = threadIdx.x;
    int b   = blockIdx.z;
    int oc0 = blockIdx.y * OCT;
    int tile = blockIdx.x;
    int ty0 = (tile / 5) * TH;
    int tx0 = (tile % 5) * TW;
    int tx = t & 31, ty = t >> 5;

    unsigned long long acc[2][6];
    #pragma unroll
    for (int pxi = 0; pxi < 2; pxi++)
        #pragma unroll
        for (int j = 0; j < 6; j++) acc[pxi][j] = 0ull;

    for (int ic0 = 0; ic0 < C; ic0 += ICT) {
        for (int idx = t; idx < ICT * (TH+2) * (TW+2); idx += 256) {
            int ic = idx / ((TH+2)*(TW+2));
            int r  = idx % ((TH+2)*(TW+2));
            int yy = r / (TW+2), xx = r % (TW+2);
            int gy = ty0 + yy - 1, gx = tx0 + xx - 1;
            float v = 0.f;
            if (gy >= 0 && gy < H && gx >= 0 && gx < W)
                v = g_off[((size_t)(b * C + ic0 + ic)) * HW + gy * W + gx];
            in_s[ic][yy][xx] = v;
        }
        for (int idx = t; idx < ICT * 9 * OCT; idx += 256) {
            int oc  = idx % OCT;
            int rest = idx / OCT;
            int tap = rest % 9;
            int ic  = rest / 9;
            w_s[(ic * 9 + tap) * OCT + oc] =
                w_com[((size_t)(oc0 + oc) * C + ic0 + ic) * 9 + tap];
        }
        __syncthreads();

        #pragma unroll
        for (int ic = 0; ic < ICT; ic++) {
            float v0[9], v1[9];
            #pragma unroll
            for (int dy = 0; dy < 3; dy++)
                #pragma unroll
                for (int dx = 0; dx < 3; dx++) {
                    v0[dy*3+dx] = in_s[ic][ty     + dy][tx+dx];
                    v1[dy*3+dx] = in_s[ic][ty + 8 + dy][tx+dx];
                }
            #pragma unroll
            for (int tap = 0; tap < 9; tap++) {
                const ulonglong2* w2 = (const ulonglong2*)(w_s + (ic*9+tap) * OCT);
                ulonglong2 wA = w2[0];
                ulonglong2 wB = w2[1];
                ulonglong2 wC = w2[2];
                unsigned long long d0 = pack2(v0[tap], v0[tap]);
                unsigned long long d1 = pack2(v1[tap], v1[tap]);
                fma2(acc[0][0], d0, wA.x); fma2(acc[0][1], d0, wA.y);
                fma2(acc[0][2], d0, wB.x); fma2(acc[0][3], d0, wB.y);
                fma2(acc[0][4], d0, wC.x); fma2(acc[0][5], d0, wC.y);
                fma2(acc[1][0], d1, wA.x); fma2(acc[1][1], d1, wA.y);
                fma2(acc[1][2], d1, wB.x); fma2(acc[1][3], d1, wB.y);
                fma2(acc[1][4], d1, wC.x); fma2(acc[1][5], d1, wC.y);
            }
        }
        __syncthreads();
    }
    #pragma unroll
    for (int pxi = 0; pxi < 2; pxi++) {
        int p = (ty0 + ty + pxi * 8) * W + tx0 + tx;
        #pragma unroll
        for (int j = 0; j < 6; j++) {
            float lo, hi;
            unpack2(acc[pxi][j], lo, hi);
            g_com[((size_t)(b * CO2 + oc0 + 2*j    )) * HW + p] = lo + b_com[oc0 + 2*j];
            g_com[((size_t)(b * CO2 + oc0 + 2*j + 1)) * HW + p] = hi + b_com[oc0 + 2*j + 1];
        }
    }
}

// ============================================================
// K34: fused sampling + DCN GEMM + relu + residual.
// Block tile 64 oc x 128 px. 36 K-chunks of 16 (one (g,k), 16 ch).
// Double-buffered smem pipeline; NHWC gathers (float4).
// Micro-tile 4 oc x 8 px, FFMA2.
// ============================================================
__global__ __launch_bounds__(256) void k34_fused(
    const float* __restrict__ fea, const float* __restrict__ b_dcn,
    float* __restrict__ out)
{
    __shared__ float b_s[2][16][NT];
    __shared__ float a_s[2][16][64];

    int t  = threadIdx.x;
    int b  = blockIdx.y;
    int n0 = blockIdx.x * NT;

    const float* comb = g_com   + (size_t)b * CO2 * HW;
    const float* ftb  = g_feaT  + (size_t)b * DG * HW * CG;

    // producer mapping: 2 layers x 128 px, 8 channels each
    int pxi   = t & 127;
    int layer = t >> 7;
    int c0    = layer * 8;
    int p     = n0 + pxi;
    int ph    = p / W;
    int pw    = p - ph * W;

    // A-loader mapping
    int a_c   = t >> 4;
    int a_oc4 = (t & 15) * 4;

    // GEMM mapping
    int tm = (t >> 4) * 4;      // oc base
    int tn = (t & 15) * 8;      // px base

    unsigned long long acc[4][4];
    #pragma unroll
    for (int i = 0; i < 4; i++)
        #pragma unroll
        for (int j = 0; j < 4; j++) acc[i][j] = 0ull;

// NOTE: all internals are _-prefixed so macro args like (gk + 1) cannot
// collide with the freshly declared local (the R3 bug: `int gk = (gk+1);`).
#define PRODUCE(GK, BUF)                                                      \
    {                                                                         \
        int _gk = (GK);                                                       \
        int _buf = (BUF);                                                     \
        int _g = _gk / 9, _k = _gk - 9 * _g;                                  \
        float _dy = comb[(size_t)(_g*18 + 2*_k    ) * HW + p];                \
        float _dx = comb[(size_t)(_g*18 + 2*_k + 1) * HW + p];                \
        float _mm = comb[(size_t)(72 + _g*9 + _k  ) * HW + p];                \
        _mm = 1.f / (1.f + expf(-_mm));                                       \
        float _py = _dy + (float)(_k / 3 - 1) + (float)ph;                    \
        float _px = _dx + (float)(_k % 3 - 1) + (float)pw;                    \
        float _y0f = floorf(_py), _x0f = floorf(_px);                         \
        float _wy = _py - _y0f, _wx = _px - _x0f;                             \
        int _y0 = (int)_y0f, _x0 = (int)_x0f;                                 \
        int _y1 = _y0 + 1,   _x1 = _x0 + 1;                                   \
        bool _vy0 = (_y0 >= 0 && _y0 < H), _vy1 = (_y1 >= 0 && _y1 < H);      \
        bool _vx0 = (_x0 >= 0 && _x0 < W), _vx1 = (_x1 >= 0 && _x1 < W);      \
        float _w00 = (1.f-_wy)*(1.f-_wx) * (float)(_vy0 && _vx0) * _mm;       \
        float _w01 = (1.f-_wy)*_wx       * (float)(_vy0 && _vx1) * _mm;       \
        float _w10 = _wy*(1.f-_wx)       * (float)(_vy1 && _vx0) * _mm;       \
        float _w11 = _wy*_wx             * (float)(_vy1 && _vx1) * _mm;       \
        int _y0c = min(max(_y0, 0), H-1), _y1c = min(max(_y1, 0), H-1);       \
        int _x0c = min(max(_x0, 0), W-1), _x1c = min(max(_x1, 0), W-1);       \
        const float* _fg  = ftb + (size_t)_g * HW * CG;                       \
        const float* _p00 = _fg + (size_t)(_y0c * W + _x0c) * CG + c0;        \
        const float* _p01 = _fg + (size_t)(_y0c * W + _x1c) * CG + c0;        \
        const float* _p10 = _fg + (size_t)(_y1c * W + _x0c) * CG + c0;        \
        const float* _p11 = _fg + (size_t)(_y1c * W + _x1c) * CG + c0;        \
        float4 _a00 = *(const float4*)_p00, _b00 = *(const float4*)(_p00+4);  \
        float4 _a01 = *(const float4*)_p01, _b01 = *(const float4*)(_p01+4);  \
        float4 _a10 = *(const float4*)_p10, _b10 = *(const float4*)(_p10+4);  \
        float4 _a11 = *(const float4*)_p11, _b11 = *(const float4*)(_p11+4);  \
        b_s[_buf][c0+0][pxi] = _w00*_a00.x+_w01*_a01.x+_w10*_a10.x+_w11*_a11.x;\
        b_s[_buf][c0+1][pxi] = _w00*_a00.y+_w01*_a01.y+_w10*_a10.y+_w11*_a11.y;\
        b_s[_buf][c0+2][pxi] = _w00*_a00.z+_w01*_a01.z+_w10*_a10.z+_w11*_a11.z;\
        b_s[_buf][c0+3][pxi] = _w00*_a00.w+_w01*_a01.w+_w10*_a10.w+_w11*_a11.w;\
        b_s[_buf][c0+4][pxi] = _w00*_b00.x+_w01*_b01.x+_w10*_b10.x+_w11*_b11.x;\
        b_s[_buf][c0+5][pxi] = _w00*_b00.y+_w01*_b01.y+_w10*_b10.y+_w11*_b11.y;\
        b_s[_buf][c0+6][pxi] = _w00*_b00.z+_w01*_b01.z+_w10*_b10.z+_w11*_b11.z;\
        b_s[_buf][c0+7][pxi] = _w00*_b00.w+_w01*_b01.w+_w10*_b10.w+_w11*_b11.w;\
        *(float4*)&a_s[_buf][a_c][a_oc4] =                                    \
            *(const float4*)(g_wt + (size_t)(_gk * 16 + a_c) * 64 + a_oc4);   \
    }

    PRODUCE(0, 0)
    __syncthreads();

    for (int gk = 0; gk < 36; gk++) {
        int cur = gk & 1;
        if (gk < 35) PRODUCE(gk + 1, cur ^ 1)

        #pragma unroll
        for (int kk = 0; kk < 16; kk++) {
            float4 a = *(const float4*)&a_s[cur][kk][tm];
            ulonglong2 bb0 = *(const ulonglong2*)&b_s[cur][kk][tn];
            ulonglong2 bb1 = *(const ulonglong2*)&b_s[cur][kk][tn + 4];
            unsigned long long a0 = pack2(a.x, a.x);
            unsigned long long a1 = pack2(a.y, a.y);
            unsigned long long a2 = pack2(a.z, a.z);
            unsigned long long a3 = pack2(a.w, a.w);
            fma2(acc[0][0], a0, bb0.x); fma2(acc[0][1], a0, bb0.y);
            fma2(acc[0][2], a0, bb1.x); fma2(acc[0][3], a0, bb1.y);
            fma2(acc[1][0], a1, bb0.x); fma2(acc[1][1], a1, bb0.y);
            fma2(acc[1][2], a1, bb1.x); fma2(acc[1][3], a1, bb1.y);
            fma2(acc[2][0], a2, bb0.x); fma2(acc[2][1], a2, bb0.y);
            fma2(acc[2][2], a2, bb1.x); fma2(acc[2][3], a2, bb1.y);
            fma2(acc[3][0], a3, bb0.x); fma2(acc[3][1], a3, bb0.y);
            fma2(acc[3][2], a3, bb1.x); fma2(acc[3][3], a3, bb1.y);
        }
        __syncthreads();
    }
#undef PRODUCE

    // ---- epilogue: bias, relu, residual ----
    #pragma unroll
    for (int i = 0; i < 4; i++) {
        int oc = tm + i;
        float bias = b_dcn[oc];
        size_t base = (size_t)(b * C + oc) * HW + n0 + tn;
        float r[8];
        #pragma unroll
        for (int j = 0; j < 4; j++) {
            float lo, hi;
            unpack2(acc[i][j], lo, hi);
            r[2*j]   = lo;
            r[2*j+1] = hi;
        }
        float4 f0 = *(const float4*)(fea + base);
        float4 f1 = *(const float4*)(fea + base + 4);
        float4 o0, o1;
        o0.x = f0.x + fmaxf(r[0] + bias, 0.f);
        o0.y = f0.y + fmaxf(r[1] + bias, 0.f);
        o0.z = f0.z + fmaxf(r[2] + bias, 0.f);
        o0.w = f0.w + fmaxf(r[3] + bias, 0.f);
        o1.x = f1.x + fmaxf(r[4] + bias, 0.f);
        o1.y = f1.y + fmaxf(r[5] + bias, 0.f);
        o1.z = f1.z + fmaxf(r[6] + bias, 0.f);
        o1.w = f1.w + fmaxf(r[7] + bias, 0.f);
        *(float4*)(out + base)     = o0;
        *(float4*)(out + base + 4) = o1;
    }
}

// ============================================================
extern "C" void kernel_launch(void* const* d_in, const int* in_sizes, int n_in,
                              void* d_out, int out_size)
{
    const float* fea      = (const float*)d_in[0];
    const float* w_off    = (const float*)d_in[1];
    const float* bn_gamma = (const float*)d_in[2];
    const float* bn_beta  = (const float*)d_in[3];
    const float* bn_mean  = (const float*)d_in[4];
    const float* bn_var   = (const float*)d_in[5];
    const float* w_com    = (const float*)d_in[6];
    const float* b_com    = (const float*)d_in[7];
    const float* w_dcn    = (const float*)d_in[8];
    const float* b_dcn    = (const float*)d_in[9];
    float* out = (float*)d_out;

    k0a_wt     <<<(JDIM * C + 255) / 256, 256>>>(w_dcn);
    k0b_feaT   <<<dim3(HW/64, DG, BATCH), 256>>>(fea);
    k1_pointwise<<<dim3(HW/256, BATCH), 256>>>(fea, w_off, bn_gamma, bn_beta, bn_mean, bn_var);
    k2_conv3x3 <<<dim3(50, CO2/OCT, BATCH), 256>>>(w_com, b_com);
    k34_fused  <<<dim3(HW/NT, BATCH), 256>>>(fea, b_dcn, out);
}

// round 5
// speedup vs baseline: 1.1209x; 1.1209x over previous
#include <cuda_runtime.h>
#include <math.h>

#define BATCH 4
#define C     64
#define H     160
#define W     160
#define HW    (H*W)
#define DG    4
#define KKTAP 9
#define CG    16
#define CO2   108    // 3*DG*KK
#define JDIM  576    // DG*CG*KK
#define NT    128    // k34 pixel tile

// ---- scratch (no cudaMalloc allowed) ----
__device__ float g_off [BATCH * C   * HW];   // 26 MB : 1x1 conv + BN output
__device__ float g_com [BATCH * CO2 * HW];   // 44 MB : 3x3 conv output
__device__ float g_wt  [JDIM * C];           // w_dcn reordered: [(g,k,c)][oc]
__device__ float g_feaT[BATCH * DG * HW * CG]; // 26 MB : fea NHWC-per-group

// ---------- packed f32x2 helpers ----------
__device__ __forceinline__ unsigned long long pack2(float lo, float hi) {
    unsigned long long r;
    asm("mov.b64 %0, {%1, %2};" : "=l"(r) : "f"(lo), "f"(hi));
    return r;
}
__device__ __forceinline__ void unpack2(unsigned long long v, float& lo, float& hi) {
    asm("mov.b64 {%0, %1}, %2;" : "=f"(lo), "=f"(hi) : "l"(v));
}
__device__ __forceinline__ void fma2(unsigned long long& d,
                                     unsigned long long a,
                                     unsigned long long b) {
    asm("fma.rn.f32x2 %0, %1, %2, %0;" : "+l"(d) : "l"(a), "l"(b));
}

// ============================================================
// K0a: reorder w_dcn[oc][(g,c,k)] -> g_wt[(g,k,c)][oc]
// ============================================================
__global__ __launch_bounds__(256) void k0a_wt(const float* __restrict__ w_dcn)
{
    int idx = blockIdx.x * 256 + threadIdx.x;
    if (idx >= JDIM * C) return;
    int row = idx >> 6;      // (g,k,c)
    int oc  = idx & 63;
    int g = row / (KKTAP * CG);
    int r = row - g * (KKTAP * CG);
    int k = r / CG;
    int c = r - k * CG;
    g_wt[idx] = w_dcn[(size_t)oc * JDIM + (g * CG + c) * KKTAP + k];
}

// ============================================================
// K0b: fea NCHW -> NHWC-per-group: g_feaT[b][g][p][c16]
// ============================================================
__global__ __launch_bounds__(256) void k0b_feaT(const float* __restrict__ fea)
{
    __shared__ float s[16][65];
    int t = threadIdx.x;
    int b = blockIdx.z, g = blockIdx.y;
    int base = blockIdx.x * 64;
    #pragma unroll
    for (int r = 0; r < 4; r++) {
        int idx = t + r * 256;
        int c = idx >> 6, p = idx & 63;
        s[c][p] = fea[((size_t)(b * C + g * CG + c)) * HW + base + p];
    }
    __syncthreads();
    int p = t >> 2, q = (t & 3) * 4;
    float4 v = make_float4(s[q][p], s[q+1][p], s[q+2][p], s[q+3][p]);
    *(float4*)(g_feaT + (((size_t)(b * DG + g) * HW) + base + p) * CG + q) = v;
}

// ============================================================
// K1: off_feat = BN(fea @ w_off)
// ============================================================
__global__ __launch_bounds__(256) void k1_pointwise(
    const float* __restrict__ fea, const float* __restrict__ w_off,
    const float* __restrict__ gamma, const float* __restrict__ beta,
    const float* __restrict__ mean, const float* __restrict__ var)
{
    __shared__ float ws[64 * 64];
    __shared__ float sc[64], sh[64];
    int t = threadIdx.x;
    for (int idx = t; idx < 4096; idx += 256) {
        int o = idx & 63, i = idx >> 6;
        ws[i * 64 + o] = w_off[o * 64 + i];
    }
    if (t < 64) {
        float inv = gamma[t] * rsqrtf(var[t] + 1e-5f);
        sc[t] = inv;
        sh[t] = beta[t] - mean[t] * inv;
    }
    __syncthreads();

    int b = blockIdx.y;
    int p = blockIdx.x * 256 + t;
    const float* fb = fea + (size_t)b * C * HW + p;

    unsigned long long acc[32];
    #pragma unroll
    for (int o = 0; o < 32; o++) acc[o] = 0ull;

    #pragma unroll 4
    for (int i = 0; i < 64; i++) {
        float a = fb[(size_t)i * HW];
        unsigned long long a2 = pack2(a, a);
        const ulonglong2* w2 = (const ulonglong2*)(ws + i * 64);
        #pragma unroll
        for (int o4 = 0; o4 < 16; o4++) {
            ulonglong2 w = w2[o4];
            fma2(acc[2*o4+0], a2, w.x);
            fma2(acc[2*o4+1], a2, w.y);
        }
    }
    float* ob = g_off + (size_t)b * C * HW + p;
    #pragma unroll
    for (int o = 0; o < 32; o++) {
        float lo, hi;
        unpack2(acc[o], lo, hi);
        ob[(size_t)(2*o  ) * HW] = lo * sc[2*o  ] + sh[2*o  ];
        ob[(size_t)(2*o+1) * HW] = hi * sc[2*o+1] + sh[2*o+1];
    }
}

// ============================================================
// K2: com = conv3x3(off_feat, w_com) + b_com   (64 -> 108 ch)
// Input tile stored PRE-DUPLICATED (float2(v,v)) so the FFMA2
// broadcast operand is a straight LDS.64 (zero pack MOVs).
// ============================================================
#define TW  32
#define TH  16
#define OCT 12
#define ICT 8

__global__ __launch_bounds__(256) void k2_conv3x3(
    const float* __restrict__ w_com, const float* __restrict__ b_com)
{
    __shared__ float2 in_s[ICT][TH+2][TW+2];      // 8*18*34*8B = 39168 B
    __shared__ float  w_s[ICT * 9 * OCT];         // [(ic*9+tap)*12 + oc]
    int t   = threadIdx.x;
    int b   = blockIdx.z;
    int oc0 = blockIdx.y * OCT;
    int tile = blockIdx.x;
    int ty0 = (tile / 5) * TH;
    int tx0 = (tile % 5) * TW;
    int tx = t & 31, ty = t >> 5;

    unsigned long long acc[2][6];
    #pragma unroll
    for (int pxi = 0; pxi < 2; pxi++)
        #pragma unroll
        for (int j = 0; j < 6; j++) acc[pxi][j] = 0ull;

    for (int ic0 = 0; ic0 < C; ic0 += ICT) {
        for (int idx = t; idx < ICT * (TH+2) * (TW+2); idx += 256) {
            int ic = idx / ((TH+2)*(TW+2));
            int r  = idx % ((TH+2)*(TW+2));
            int yy = r / (TW+2), xx = r % (TW+2);
            int gy = ty0 + yy - 1, gx = tx0 + xx - 1;
            float v = 0.f;
            if (gy >= 0 && gy < H && gx >= 0 && gx < W)
                v = g_off[((size_t)(b * C + ic0 + ic)) * HW + gy * W + gx];
            in_s[ic][yy][xx] = make_float2(v, v);
        }
        for (int idx = t; idx < ICT * 9 * OCT; idx += 256) {
            int oc  = idx % OCT;
            int rest = idx / OCT;
            int tap = rest % 9;
            int ic  = rest / 9;
            w_s[(ic * 9 + tap) * OCT + oc] =
                w_com[((size_t)(oc0 + oc) * C + ic0 + ic) * 9 + tap];
        }
        __syncthreads();

        #pragma unroll
        for (int ic = 0; ic < ICT; ic++) {
            unsigned long long d0[9], d1[9];
            #pragma unroll
            for (int dy = 0; dy < 3; dy++)
                #pragma unroll
                for (int dx = 0; dx < 3; dx++) {
                    d0[dy*3+dx] = *(const unsigned long long*)&in_s[ic][ty     + dy][tx+dx];
                    d1[dy*3+dx] = *(const unsigned long long*)&in_s[ic][ty + 8 + dy][tx+dx];
                }
            #pragma unroll
            for (int tap = 0; tap < 9; tap++) {
                const ulonglong2* w2 = (const ulonglong2*)(w_s + (ic*9+tap) * OCT);
                ulonglong2 wA = w2[0];
                ulonglong2 wB = w2[1];
                ulonglong2 wC = w2[2];
                fma2(acc[0][0], d0[tap], wA.x); fma2(acc[0][1], d0[tap], wA.y);
                fma2(acc[0][2], d0[tap], wB.x); fma2(acc[0][3], d0[tap], wB.y);
                fma2(acc[0][4], d0[tap], wC.x); fma2(acc[0][5], d0[tap], wC.y);
                fma2(acc[1][0], d1[tap], wA.x); fma2(acc[1][1], d1[tap], wA.y);
                fma2(acc[1][2], d1[tap], wB.x); fma2(acc[1][3], d1[tap], wB.y);
                fma2(acc[1][4], d1[tap], wC.x); fma2(acc[1][5], d1[tap], wC.y);
            }
        }
        __syncthreads();
    }
    #pragma unroll
    for (int pxi = 0; pxi < 2; pxi++) {
        int p = (ty0 + ty + pxi * 8) * W + tx0 + tx;
        #pragma unroll
        for (int j = 0; j < 6; j++) {
            float lo, hi;
            unpack2(acc[pxi][j], lo, hi);
            g_com[((size_t)(b * CO2 + oc0 + 2*j    )) * HW + p] = lo + b_com[oc0 + 2*j];
            g_com[((size_t)(b * CO2 + oc0 + 2*j + 1)) * HW + p] = hi + b_com[oc0 + 2*j + 1];
        }
    }
}

// ============================================================
// K34: fused sampling + DCN GEMM + relu + residual.
// Block tile 64 oc x 128 px. 36 K-chunks of 16 (one (g,k), 16 ch).
// Micro-tile: 4 oc x (4 + 4) px — two dense pixel quads at
// tn4 and 64+tn4 so B reads are stride-16B conflict-free LDS.128.
// ============================================================
__global__ __launch_bounds__(256) void k34_fused(
    const float* __restrict__ fea, const float* __restrict__ b_dcn,
    float* __restrict__ out)
{
    __shared__ float b_s[2][16][NT];
    __shared__ float a_s[2][16][64];

    int t  = threadIdx.x;
    int b  = blockIdx.y;
    int n0 = blockIdx.x * NT;

    const float* comb = g_com   + (size_t)b * CO2 * HW;
    const float* ftb  = g_feaT  + (size_t)b * DG * HW * CG;

    // producer mapping: 2 layers x 128 px, 8 channels each
    int pxi   = t & 127;
    int layer = t >> 7;
    int c0    = layer * 8;
    int p     = n0 + pxi;
    int ph    = p / W;
    int pw    = p - ph * W;

    // A-loader mapping
    int a_c   = t >> 4;
    int a_oc4 = (t & 15) * 4;

    // GEMM mapping
    int tm  = (t >> 4) * 4;     // oc base
    int tn4 = (t & 15) * 4;     // pixel quad base (second quad at +64)

    unsigned long long acc[4][4];
    #pragma unroll
    for (int i = 0; i < 4; i++)
        #pragma unroll
        for (int j = 0; j < 4; j++) acc[i][j] = 0ull;

// all internals _-prefixed: macro args like (gk+1) must not collide with
// freshly declared locals (R3 bug: `int gk = (gk+1);`).
#define PRODUCE(GK, BUF)                                                      \
    {                                                                         \
        int _gk = (GK);                                                       \
        int _buf = (BUF);                                                     \
        int _g = _gk / 9, _k = _gk - 9 * _g;                                  \
        float _dy = comb[(size_t)(_g*18 + 2*_k    ) * HW + p];                \
        float _dx = comb[(size_t)(_g*18 + 2*_k + 1) * HW + p];                \
        float _mm = comb[(size_t)(72 + _g*9 + _k  ) * HW + p];                \
        _mm = 1.f / (1.f + expf(-_mm));                                       \
        float _py = _dy + (float)(_k / 3 - 1) + (float)ph;                    \
        float _px = _dx + (float)(_k % 3 - 1) + (float)pw;                    \
        float _y0f = floorf(_py), _x0f = floorf(_px);                         \
        float _wy = _py - _y0f, _wx = _px - _x0f;                             \
        int _y0 = (int)_y0f, _x0 = (int)_x0f;                                 \
        int _y1 = _y0 + 1,   _x1 = _x0 + 1;                                   \
        bool _vy0 = (_y0 >= 0 && _y0 < H), _vy1 = (_y1 >= 0 && _y1 < H);      \
        bool _vx0 = (_x0 >= 0 && _x0 < W), _vx1 = (_x1 >= 0 && _x1 < W);      \
        float _w00 = (1.f-_wy)*(1.f-_wx) * (float)(_vy0 && _vx0) * _mm;       \
        float _w01 = (1.f-_wy)*_wx       * (float)(_vy0 && _vx1) * _mm;       \
        float _w10 = _wy*(1.f-_wx)       * (float)(_vy1 && _vx0) * _mm;       \
        float _w11 = _wy*_wx             * (float)(_vy1 && _vx1) * _mm;       \
        int _y0c = min(max(_y0, 0), H-1), _y1c = min(max(_y1, 0), H-1);       \
        int _x0c = min(max(_x0, 0), W-1), _x1c = min(max(_x1, 0), W-1);       \
        const float* _fg  = ftb + (size_t)_g * HW * CG;                       \
        const float* _p00 = _fg + (size_t)(_y0c * W + _x0c) * CG + c0;        \
        const float* _p01 = _fg + (size_t)(_y0c * W + _x1c) * CG + c0;        \
        const float* _p10 = _fg + (size_t)(_y1c * W + _x0c) * CG + c0;        \
        const float* _p11 = _fg + (size_t)(_y1c * W + _x1c) * CG + c0;        \
        float4 _a00 = *(const float4*)_p00, _b00 = *(const float4*)(_p00+4);  \
        float4 _a01 = *(const float4*)_p01, _b01 = *(const float4*)(_p01+4);  \
        float4 _a10 = *(const float4*)_p10, _b10 = *(const float4*)(_p10+4);  \
        float4 _a11 = *(const float4*)_p11, _b11 = *(const float4*)(_p11+4);  \
        b_s[_buf][c0+0][pxi] = _w00*_a00.x+_w01*_a01.x+_w10*_a10.x+_w11*_a11.x;\
        b_s[_buf][c0+1][pxi] = _w00*_a00.y+_w01*_a01.y+_w10*_a10.y+_w11*_a11.y;\
        b_s[_buf][c0+2][pxi] = _w00*_a00.z+_w01*_a01.z+_w10*_a10.z+_w11*_a11.z;\
        b_s[_buf][c0+3][pxi] = _w00*_a00.w+_w01*_a01.w+_w10*_a10.w+_w11*_a11.w;\
        b_s[_buf][c0+4][pxi] = _w00*_b00.x+_w01*_b01.x+_w10*_b10.x+_w11*_b11.x;\
        b_s[_buf][c0+5][pxi] = _w00*_b00.y+_w01*_b01.y+_w10*_b10.y+_w11*_b11.y;\
        b_s[_buf][c0+6][pxi] = _w00*_b00.z+_w01*_b01.z+_w10*_b10.z+_w11*_b11.z;\
        b_s[_buf][c0+7][pxi] = _w00*_b00.w+_w01*_b01.w+_w10*_b10.w+_w11*_b11.w;\
        *(float4*)&a_s[_buf][a_c][a_oc4] =                                    \
            *(const float4*)(g_wt + (size_t)(_gk * 16 + a_c) * 64 + a_oc4);   \
    }

    PRODUCE(0, 0)
    __syncthreads();

    for (int gk = 0; gk < 36; gk++) {
        int cur = gk & 1;
        if (gk < 35) PRODUCE(gk + 1, cur ^ 1)

        #pragma unroll
        for (int kk = 0; kk < 16; kk++) {
            float4 a = *(const float4*)&a_s[cur][kk][tm];
            ulonglong2 bb0 = *(const ulonglong2*)&b_s[cur][kk][tn4];       // px quad 0
            ulonglong2 bb1 = *(const ulonglong2*)&b_s[cur][kk][64 + tn4];  // px quad 1
            unsigned long long a0 = pack2(a.x, a.x);
            unsigned long long a1 = pack2(a.y, a.y);
            unsigned long long a2 = pack2(a.z, a.z);
            unsigned long long a3 = pack2(a.w, a.w);
            fma2(acc[0][0], a0, bb0.x); fma2(acc[0][1], a0, bb0.y);
            fma2(acc[0][2], a0, bb1.x); fma2(acc[0][3], a0, bb1.y);
            fma2(acc[1][0], a1, bb0.x); fma2(acc[1][1], a1, bb0.y);
            fma2(acc[1][2], a1, bb1.x); fma2(acc[1][3], a1, bb1.y);
            fma2(acc[2][0], a2, bb0.x); fma2(acc[2][1], a2, bb0.y);
            fma2(acc[2][2], a2, bb1.x); fma2(acc[2][3], a2, bb1.y);
            fma2(acc[3][0], a3, bb0.x); fma2(acc[3][1], a3, bb0.y);
            fma2(acc[3][2], a3, bb1.x); fma2(acc[3][3], a3, bb1.y);
        }
        __syncthreads();
    }
#undef PRODUCE

    // ---- epilogue: bias, relu, residual (two pixel quads) ----
    #pragma unroll
    for (int i = 0; i < 4; i++) {
        int oc = tm + i;
        float bias = b_dcn[oc];
        size_t base = (size_t)(b * C + oc) * HW + n0;
        float lo, hi;
        float4 f0 = *(const float4*)(fea + base + tn4);
        float4 f1 = *(const float4*)(fea + base + 64 + tn4);
        float4 o0, o1;
        unpack2(acc[i][0], lo, hi);
        o0.x = f0.x + fmaxf(lo + bias, 0.f);
        o0.y = f0.y + fmaxf(hi + bias, 0.f);
        unpack2(acc[i][1], lo, hi);
        o0.z = f0.z + fmaxf(lo + bias, 0.f);
        o0.w = f0.w + fmaxf(hi + bias, 0.f);
        unpack2(acc[i][2], lo, hi);
        o1.x = f1.x + fmaxf(lo + bias, 0.f);
        o1.y = f1.y + fmaxf(hi + bias, 0.f);
        unpack2(acc[i][3], lo, hi);
        o1.z = f1.z + fmaxf(lo + bias, 0.f);
        o1.w = f1.w + fmaxf(hi + bias, 0.f);
        *(float4*)(out + base + tn4)      = o0;
        *(float4*)(out + base + 64 + tn4) = o1;
    }
}

// ============================================================
extern "C" void kernel_launch(void* const* d_in, const int* in_sizes, int n_in,
                              void* d_out, int out_size)
{
    const float* fea      = (const float*)d_in[0];
    const float* w_off    = (const float*)d_in[1];
    const float* bn_gamma = (const float*)d_in[2];
    const float* bn_beta  = (const float*)d_in[3];
    const float* bn_mean  = (const float*)d_in[4];
    const float* bn_var   = (const float*)d_in[5];
    const float* w_com    = (const float*)d_in[6];
    const float* b_com    = (const float*)d_in[7];
    const float* w_dcn    = (const float*)d_in[8];
    const float* b_dcn    = (const float*)d_in[9];
    float* out = (float*)d_out;

    k0a_wt     <<<(JDIM * C + 255) / 256, 256>>>(w_dcn);
    k0b_feaT   <<<dim3(HW/64, DG, BATCH), 256>>>(fea);
    k1_pointwise<<<dim3(HW/256, BATCH), 256>>>(fea, w_off, bn_gamma, bn_beta, bn_mean, bn_var);
    k2_conv3x3 <<<dim3(50, CO2/OCT, BATCH), 256>>>(w_com, b_com);
    k34_fused  <<<dim3(HW/NT, BATCH), 256>>>(fea, b_dcn, out);
}

// round 6
// speedup vs baseline: 1.2858x; 1.1471x over previous
#include <cuda_runtime.h>
#include <math.h>

#define BATCH 4
#define C     64
#define H     160
#define W     160
#define HW    (H*W)
#define DG    4
#define KKTAP 9
#define CG    16
#define CO2   108    // 3*DG*KK
#define JDIM  576    // DG*CG*KK
#define NT    128    // k34 pixel tile

// ---- scratch (no cudaMalloc allowed) ----
__device__ float g_off [BATCH * C   * HW];
__device__ float g_com [BATCH * CO2 * HW];
__device__ float g_wt  [JDIM * C];             // w_dcn reordered: [(g,k,c)][oc]
__device__ float g_feaT[BATCH * DG * HW * CG]; // fea NHWC-per-group

// ---------- packed f32x2 helpers ----------
__device__ __forceinline__ unsigned long long pack2(float lo, float hi) {
    unsigned long long r;
    asm("mov.b64 %0, {%1, %2};" : "=l"(r) : "f"(lo), "f"(hi));
    return r;
}
__device__ __forceinline__ void unpack2(unsigned long long v, float& lo, float& hi) {
    asm("mov.b64 {%0, %1}, %2;" : "=f"(lo), "=f"(hi) : "l"(v));
}
__device__ __forceinline__ void fma2(unsigned long long& d,
                                     unsigned long long a,
                                     unsigned long long b) {
    asm("fma.rn.f32x2 %0, %1, %2, %0;" : "+l"(d) : "l"(a), "l"(b));
}

// ============================================================
// K0a: reorder w_dcn[oc][(g,c,k)] -> g_wt[(g,k,c)][oc]
// ============================================================
__global__ __launch_bounds__(256) void k0a_wt(const float* __restrict__ w_dcn)
{
    int idx = blockIdx.x * 256 + threadIdx.x;
    if (idx >= JDIM * C) return;
    int row = idx >> 6;      // (g,k,c)
    int oc  = idx & 63;
    int g = row / (KKTAP * CG);
    int r = row - g * (KKTAP * CG);
    int k = r / CG;
    int c = r - k * CG;
    g_wt[idx] = w_dcn[(size_t)oc * JDIM + (g * CG + c) * KKTAP + k];
}

// ============================================================
// K0b: fea NCHW -> NHWC-per-group: g_feaT[b][g][p][c16]
// ============================================================
__global__ __launch_bounds__(256) void k0b_feaT(const float* __restrict__ fea)
{
    __shared__ float s[16][65];
    int t = threadIdx.x;
    int b = blockIdx.z, g = blockIdx.y;
    int base = blockIdx.x * 64;
    #pragma unroll
    for (int r = 0; r < 4; r++) {
        int idx = t + r * 256;
        int c = idx >> 6, p = idx & 63;
        s[c][p] = fea[((size_t)(b * C + g * CG + c)) * HW + base + p];
    }
    __syncthreads();
    int p = t >> 2, q = (t & 3) * 4;
    float4 v = make_float4(s[q][p], s[q+1][p], s[q+2][p], s[q+3][p]);
    *(float4*)(g_feaT + (((size_t)(b * DG + g) * HW) + base + p) * CG + q) = v;
}

// ============================================================
// K1: off_feat = BN(fea @ w_off)
// ============================================================
__global__ __launch_bounds__(256) void k1_pointwise(
    const float* __restrict__ fea, const float* __restrict__ w_off,
    const float* __restrict__ gamma, const float* __restrict__ beta,
    const float* __restrict__ mean, const float* __restrict__ var)
{
    __shared__ float ws[64 * 64];
    __shared__ float sc[64], sh[64];
    int t = threadIdx.x;
    for (int idx = t; idx < 4096; idx += 256) {
        int o = idx & 63, i = idx >> 6;
        ws[i * 64 + o] = w_off[o * 64 + i];
    }
    if (t < 64) {
        float inv = gamma[t] * rsqrtf(var[t] + 1e-5f);
        sc[t] = inv;
        sh[t] = beta[t] - mean[t] * inv;
    }
    __syncthreads();

    int b = blockIdx.y;
    int p = blockIdx.x * 256 + t;
    const float* fb = fea + (size_t)b * C * HW + p;

    unsigned long long acc[32];
    #pragma unroll
    for (int o = 0; o < 32; o++) acc[o] = 0ull;

    #pragma unroll 4
    for (int i = 0; i < 64; i++) {
        float a = fb[(size_t)i * HW];
        unsigned long long a2 = pack2(a, a);
        const ulonglong2* w2 = (const ulonglong2*)(ws + i * 64);
        #pragma unroll
        for (int o4 = 0; o4 < 16; o4++) {
            ulonglong2 w = w2[o4];
            fma2(acc[2*o4+0], a2, w.x);
            fma2(acc[2*o4+1], a2, w.y);
        }
    }
    float* ob = g_off + (size_t)b * C * HW + p;
    #pragma unroll
    for (int o = 0; o < 32; o++) {
        float lo, hi;
        unpack2(acc[o], lo, hi);
        ob[(size_t)(2*o  ) * HW] = lo * sc[2*o  ] + sh[2*o  ];
        ob[(size_t)(2*o+1) * HW] = hi * sc[2*o+1] + sh[2*o+1];
    }
}

// ============================================================
// K2: com = conv3x3(off_feat, w_com) + b_com   (64 -> 108 ch)
// 32x32 spatial tile, 4 px/thread (rows ty+{0,8,16,24}), 12 oc.
// Div-free vectorized loaders; FFMA2 inner loop.
// smem halo tile: 8 ic x 34 rows x 40 cols (cols tx0-4 .. tx0+35).
// ============================================================
#define K2_ICT 8

__global__ __launch_bounds__(256, 2) void k2_conv3x3(
    const float* __restrict__ w_com, const float* __restrict__ b_com)
{
    __shared__ float in_s[K2_ICT][34][40];   // 43520 B
    __shared__ float w_s[K2_ICT * 9 * 12];   // [(ic*9+tap)*12 + oc], 3456 B

    int t    = threadIdx.x;
    int b    = blockIdx.z;
    int oc0  = blockIdx.y * 12;
    int tile = blockIdx.x;                   // 0..24
    int ty0  = (tile / 5) * 32;
    int tx0  = (tile % 5) * 32;
    int tx   = t & 31, ty = t >> 5;          // ty = warp id (0..7)

    // loader lane mapping (input): warp ty loads plane ic=ty.
    int lq    = t & 15;        // quad index 0..9 (idle if >=10)
    int lhalf = (t >> 4) & 1;  // row parity within pair

    unsigned long long acc[4][6];
    #pragma unroll
    for (int j = 0; j < 4; j++)
        #pragma unroll
        for (int o = 0; o < 6; o++) acc[j][o] = 0ull;

    for (int ic0 = 0; ic0 < C; ic0 += K2_ICT) {
        // ---- input halo tile: warp per plane, float4 quads ----
        {
            const float* src = g_off + ((size_t)(b * C + ic0 + ty)) * HW;
            int gxq = tx0 - 4 + 4 * lq;                  // quad col (mult of 4)
            bool qok = (lq < 10) && ((unsigned)gxq < (unsigned)W);
            #pragma unroll
            for (int r = 0; r < 34; r += 2) {
                int row = r + lhalf;
                int gy  = ty0 + row - 1;
                float4 v = make_float4(0.f, 0.f, 0.f, 0.f);
                if (qok && (unsigned)gy < (unsigned)H)
                    v = *(const float4*)(src + (size_t)gy * W + gxq);
                if (lq < 10)
                    *(float4*)&in_s[ty][row][4 * lq] = v;
            }
        }
        // ---- weights: target idx = (ic*9+tap)*12 + oc = r*12 + oc ----
        #pragma unroll
        for (int rep = 0; rep < 4; rep++) {
            int idx = t + rep * 256;
            if (idx < K2_ICT * 9 * 12) {
                int oc = idx % 12;
                int r  = idx / 12;           // r = ic*9 + tap (0..71)
                w_s[idx] = w_com[((size_t)(oc0 + oc)) * (C * 9) + ic0 * 9 + r];
            }
        }
        __syncthreads();

        #pragma unroll
        for (int ic = 0; ic < K2_ICT; ic++) {
            #pragma unroll
            for (int dy = 0; dy < 3; dy++) {
                // values: 4 px-rows x 3 cols
                float va[4][3];
                #pragma unroll
                for (int j = 0; j < 4; j++) {
                    const float* rw = &in_s[ic][ty + 8*j + dy][tx + 3];
                    va[j][0] = rw[0]; va[j][1] = rw[1]; va[j][2] = rw[2];
                }
                #pragma unroll
                for (int dx = 0; dx < 3; dx++) {
                    int tap = dy * 3 + dx;
                    const ulonglong2* w2 = (const ulonglong2*)(w_s + (ic*9 + tap) * 12);
                    ulonglong2 wA = w2[0];   // oc 0-3
                    ulonglong2 wB = w2[1];   // oc 4-7
                    ulonglong2 wC = w2[2];   // oc 8-11
                    #pragma unroll
                    for (int j = 0; j < 4; j++) {
                        unsigned long long d = pack2(va[j][dx], va[j][dx]);
                        fma2(acc[j][0], d, wA.x); fma2(acc[j][1], d, wA.y);
                        fma2(acc[j][2], d, wB.x); fma2(acc[j][3], d, wB.y);
                        fma2(acc[j][4], d, wC.x); fma2(acc[j][5], d, wC.y);
                    }
                }
            }
        }
        __syncthreads();
    }

    // ---- epilogue ----
    #pragma unroll
    for (int j = 0; j < 4; j++) {
        int p = (ty0 + ty + 8*j) * W + tx0 + tx;
        #pragma unroll
        for (int o = 0; o < 6; o++) {
            float lo, hi;
            unpack2(acc[j][o], lo, hi);
            g_com[((size_t)(b * CO2 + oc0 + 2*o    )) * HW + p] = lo + b_com[oc0 + 2*o];
            g_com[((size_t)(b * CO2 + oc0 + 2*o + 1)) * HW + p] = hi + b_com[oc0 + 2*o + 1];
        }
    }
}

// ============================================================
// K34: fused sampling + DCN GEMM + relu + residual.
// Block tile 64 oc x 128 px; 36 K-chunks of 16 (one (g,k), 16 ch).
// Double-buffered; NHWC float4 gathers; micro-tile 4 oc x (4+4) px
// with conflict-free stride-16B LDS.128 B reads.
// ============================================================
__global__ __launch_bounds__(256) void k34_fused(
    const float* __restrict__ fea, const float* __restrict__ b_dcn,
    float* __restrict__ out)
{
    __shared__ float b_s[2][16][NT];
    __shared__ float a_s[2][16][64];

    int t  = threadIdx.x;
    int b  = blockIdx.y;
    int n0 = blockIdx.x * NT;

    const float* comb = g_com   + (size_t)b * CO2 * HW;
    const float* ftb  = g_feaT  + (size_t)b * DG * HW * CG;

    int pxi   = t & 127;
    int layer = t >> 7;
    int c0    = layer * 8;
    int p     = n0 + pxi;
    int ph    = p / W;
    int pw    = p - ph * W;

    int a_c   = t >> 4;
    int a_oc4 = (t & 15) * 4;

    int tm  = (t >> 4) * 4;     // oc base
    int tn4 = (t & 15) * 4;     // pixel quad base (second quad at +64)

    unsigned long long acc[4][4];
    #pragma unroll
    for (int i = 0; i < 4; i++)
        #pragma unroll
        for (int j = 0; j < 4; j++) acc[i][j] = 0ull;

// all internals _-prefixed: macro args like (gk+1) must not collide with
// freshly declared locals.
#define PRODUCE(GK, BUF)                                                      \
    {                                                                         \
        int _gk = (GK);                                                       \
        int _buf = (BUF);                                                     \
        int _g = _gk / 9, _k = _gk - 9 * _g;                                  \
        float _dy = comb[(size_t)(_g*18 + 2*_k    ) * HW + p];                \
        float _dx = comb[(size_t)(_g*18 + 2*_k + 1) * HW + p];                \
        float _mm = comb[(size_t)(72 + _g*9 + _k  ) * HW + p];                \
        _mm = 1.f / (1.f + expf(-_mm));                                       \
        float _py = _dy + (float)(_k / 3 - 1) + (float)ph;                    \
        float _px = _dx + (float)(_k % 3 - 1) + (float)pw;                    \
        float _y0f = floorf(_py), _x0f = floorf(_px);                         \
        float _wy = _py - _y0f, _wx = _px - _x0f;                             \
        int _y0 = (int)_y0f, _x0 = (int)_x0f;                                 \
        int _y1 = _y0 + 1,   _x1 = _x0 + 1;                                   \
        bool _vy0 = (_y0 >= 0 && _y0 < H), _vy1 = (_y1 >= 0 && _y1 < H);      \
        bool _vx0 = (_x0 >= 0 && _x0 < W), _vx1 = (_x1 >= 0 && _x1 < W);      \
        float _w00 = (1.f-_wy)*(1.f-_wx) * (float)(_vy0 && _vx0) * _mm;       \
        float _w01 = (1.f-_wy)*_wx       * (float)(_vy0 && _vx1) * _mm;       \
        float _w10 = _wy*(1.f-_wx)       * (float)(_vy1 && _vx0) * _mm;       \
        float _w11 = _wy*_wx             * (float)(_vy1 && _vx1) * _mm;       \
        int _y0c = min(max(_y0, 0), H-1), _y1c = min(max(_y1, 0), H-1);       \
        int _x0c = min(max(_x0, 0), W-1), _x1c = min(max(_x1, 0), W-1);       \
        const float* _fg  = ftb + (size_t)_g * HW * CG;                       \
        const float* _p00 = _fg + (size_t)(_y0c * W + _x0c) * CG + c0;        \
        const float* _p01 = _fg + (size_t)(_y0c * W + _x1c) * CG + c0;        \
        const float* _p10 = _fg + (size_t)(_y1c * W + _x0c) * CG + c0;        \
        const float* _p11 = _fg + (size_t)(_y1c * W + _x1c) * CG + c0;        \
        float4 _a00 = *(const float4*)_p00, _b00 = *(const float4*)(_p00+4);  \
        float4 _a01 = *(const float4*)_p01, _b01 = *(const float4*)(_p01+4);  \
        float4 _a10 = *(const float4*)_p10, _b10 = *(const float4*)(_p10+4);  \
        float4 _a11 = *(const float4*)_p11, _b11 = *(const float4*)(_p11+4);  \
        b_s[_buf][c0+0][pxi] = _w00*_a00.x+_w01*_a01.x+_w10*_a10.x+_w11*_a11.x;\
        b_s[_buf][c0+1][pxi] = _w00*_a00.y+_w01*_a01.y+_w10*_a10.y+_w11*_a11.y;\
        b_s[_buf][c0+2][pxi] = _w00*_a00.z+_w01*_a01.z+_w10*_a10.z+_w11*_a11.z;\
        b_s[_buf][c0+3][pxi] = _w00*_a00.w+_w01*_a01.w+_w10*_a10.w+_w11*_a11.w;\
        b_s[_buf][c0+4][pxi] = _w00*_b00.x+_w01*_b01.x+_w10*_b10.x+_w11*_b11.x;\
        b_s[_buf][c0+5][pxi] = _w00*_b00.y+_w01*_b01.y+_w10*_b10.y+_w11*_b11.y;\
        b_s[_buf][c0+6][pxi] = _w00*_b00.z+_w01*_b01.z+_w10*_b10.z+_w11*_b11.z;\
        b_s[_buf][c0+7][pxi] = _w00*_b00.w+_w01*_b01.w+_w10*_b10.w+_w11*_b11.w;\
        *(float4*)&a_s[_buf][a_c][a_oc4] =                                    \
            *(const float4*)(g_wt + (size_t)(_gk * 16 + a_c) * 64 + a_oc4);   \
    }

    PRODUCE(0, 0)
    __syncthreads();

    for (int gk = 0; gk < 36; gk++) {
        int cur = gk & 1;
        if (gk < 35) PRODUCE(gk + 1, cur ^ 1)

        #pragma unroll
        for (int kk = 0; kk < 16; kk++) {
            float4 a = *(const float4*)&a_s[cur][kk][tm];
            ulonglong2 bb0 = *(const ulonglong2*)&b_s[cur][kk][tn4];
            ulonglong2 bb1 = *(const ulonglong2*)&b_s[cur][kk][64 + tn4];
            unsigned long long a0 = pack2(a.x, a.x);
            unsigned long long a1 = pack2(a.y, a.y);
            unsigned long long a2 = pack2(a.z, a.z);
            unsigned long long a3 = pack2(a.w, a.w);
            fma2(acc[0][0], a0, bb0.x); fma2(acc[0][1], a0, bb0.y);
            fma2(acc[0][2], a0, bb1.x); fma2(acc[0][3], a0, bb1.y);
            fma2(acc[1][0], a1, bb0.x); fma2(acc[1][1], a1, bb0.y);
            fma2(acc[1][2], a1, bb1.x); fma2(acc[1][3], a1, bb1.y);
            fma2(acc[2][0], a2, bb0.x); fma2(acc[2][1], a2, bb0.y);
            fma2(acc[2][2], a2, bb1.x); fma2(acc[2][3], a2, bb1.y);
            fma2(acc[3][0], a3, bb0.x); fma2(acc[3][1], a3, bb0.y);
            fma2(acc[3][2], a3, bb1.x); fma2(acc[3][3], a3, bb1.y);
        }
        __syncthreads();
    }
#undef PRODUCE

    // ---- epilogue: bias, relu, residual (two pixel quads) ----
    #pragma unroll
    for (int i = 0; i < 4; i++) {
        int oc = tm + i;
        float bias = b_dcn[oc];
        size_t base = (size_t)(b * C + oc) * HW + n0;
        float lo, hi;
        float4 f0 = *(const float4*)(fea + base + tn4);
        float4 f1 = *(const float4*)(fea + base + 64 + tn4);
        float4 o0, o1;
        unpack2(acc[i][0], lo, hi);
        o0.x = f0.x + fmaxf(lo + bias, 0.f);
        o0.y = f0.y + fmaxf(hi + bias, 0.f);
        unpack2(acc[i][1], lo, hi);
        o0.z = f0.z + fmaxf(lo + bias, 0.f);
        o0.w = f0.w + fmaxf(hi + bias, 0.f);
        unpack2(acc[i][2], lo, hi);
        o1.x = f1.x + fmaxf(lo + bias, 0.f);
        o1.y = f1.y + fmaxf(hi + bias, 0.f);
        unpack2(acc[i][3], lo, hi);
        o1.z = f1.z + fmaxf(lo + bias, 0.f);
        o1.w = f1.w + fmaxf(hi + bias, 0.f);
        *(float4*)(out + base + tn4)      = o0;
        *(float4*)(out + base + 64 + tn4) = o1;
    }
}

// ============================================================
extern "C" void kernel_launch(void* const* d_in, const int* in_sizes, int n_in,
                              void* d_out, int out_size)
{
    const float* fea      = (const float*)d_in[0];
    const float* w_off    = (const float*)d_in[1];
    const float* bn_gamma = (const float*)d_in[2];
    const float* bn_beta  = (const float*)d_in[3];
    const float* bn_mean  = (const float*)d_in[4];
    const float* bn_var   = (const float*)d_in[5];
    const float* w_com    = (const float*)d_in[6];
    const float* b_com    = (const float*)d_in[7];
    const float* w_dcn    = (const float*)d_in[8];
    const float* b_dcn    = (const float*)d_in[9];
    float* out = (float*)d_out;

    k0a_wt     <<<(JDIM * C + 255) / 256, 256>>>(w_dcn);
    k0b_feaT   <<<dim3(HW/64, DG, BATCH), 256>>>(fea);
    k1_pointwise<<<dim3(HW/256, BATCH), 256>>>(fea, w_off, bn_gamma, bn_beta, bn_mean, bn_var);
    k2_conv3x3 <<<dim3(25, CO2/12, BATCH), 256>>>(w_com, b_com);
    k34_fused  <<<dim3(HW/NT, BATCH), 256>>>(fea, b_dcn, out);
}